// round 15
// baseline (speedup 1.0000x reference)
#include <cuda_runtime.h>
#include <cuda_bf16.h>
#include <cstdint>

// Problem constants (fixed by the reference)
#define B_    4
#define C_    512
#define H_    64
#define W_    208
#define HID_  512
#define DS_   16
#define NREG_ 4

// Setup: one block per (r, ctile-of-64) = 32 blocks + 4 perm blocks.
#define CTIL_  8                               // C_/64
#define NBLKS_ (NREG_ * CTIL_)                 // 32
#define NBLKF_ (NBLKS_ + B_)                   // 36

// Scratch (device globals; no allocation allowed)
__device__ float g_delta[B_ * NREG_ * C_];    // delta[b, r, c]
__device__ int2  g_lut  [B_ * W_];            // out col w -> (src col, reg*C_)

// ---------------------------------------------------------------------------
// Fused one-wave setup: NO inter-block dependency.
//  Block (r, ct) does BOTH stages internally:
//   Phase A: tmp[b][d] = sum_h tf[r,b,h] * Wv[r,h,d]   (full d=512, smem)
//   Phase B: delta[b,r, ct*64..] = sum_d tmp[b][d] * Wo[r,d, ct*64..]
//  Wv[r] is read by 8 blocks -> 7/8 of reads are L2 hits (Wv = 4MB << L2).
//  Blocks [32,36): perm stable counting-sort rank -> packed (src, reg*C_).
// ---------------------------------------------------------------------------
__global__ __launch_bounds__(512) void setup_fused(
        const float* __restrict__ text_feat,
        const float* __restrict__ Wv,
        const float* __restrict__ Wo,
        const int*   __restrict__ text_mask) {
    __shared__ float s_tf [B_][HID_];           // 8 KB
    __shared__ float s_red[4][B_][HID_];        // 32 KB (phase A: [hs][b][d];
                                                //         phase B: [ds][b][c64] view)
    __shared__ float s_tmp[B_][HID_];           // 8 KB
    // total 48 KB static

    const int blk = blockIdx.x;
    const int tid = threadIdx.x;

    if (blk < NBLKS_) {
        const int r  = blk / CTIL_;
        const int ct = blk % CTIL_;

        // load tf[r, b, :] for all b
        for (int i = tid; i < B_ * HID_; i += 512)
            s_tf[i / HID_][i % HID_] = text_feat[(size_t)r * B_ * HID_ + i];
        __syncthreads();

        // ---------------- Phase A: tmp[b][d], all 512 d ----------------
        {
            const int dl = tid & 127;           // d4-group: cols dl*4..dl*4+3
            const int hs = tid >> 7;            // 0..3
            const float* wv = Wv + (size_t)r * HID_ * HID_ + dl * 4;

            float4 acc[B_];
            #pragma unroll
            for (int b = 0; b < B_; ++b) acc[b] = make_float4(0.f, 0.f, 0.f, 0.f);

            #pragma unroll 8
            for (int h = hs; h < HID_; h += 4) {
                const float4 w = *reinterpret_cast<const float4*>(wv + (size_t)h * HID_);
                #pragma unroll
                for (int b = 0; b < B_; ++b) {
                    const float v = s_tf[b][h];
                    acc[b].x = fmaf(v, w.x, acc[b].x);
                    acc[b].y = fmaf(v, w.y, acc[b].y);
                    acc[b].z = fmaf(v, w.z, acc[b].z);
                    acc[b].w = fmaf(v, w.w, acc[b].w);
                }
            }
            #pragma unroll
            for (int b = 0; b < B_; ++b) {
                s_red[hs][b][dl * 4 + 0] = acc[b].x;
                s_red[hs][b][dl * 4 + 1] = acc[b].y;
                s_red[hs][b][dl * 4 + 2] = acc[b].z;
                s_red[hs][b][dl * 4 + 3] = acc[b].w;
            }
            __syncthreads();

            // reduce 4 subgroups: thread d = tid (512), all b
            #pragma unroll
            for (int b = 0; b < B_; ++b)
                s_tmp[b][tid] = s_red[0][b][tid] + s_red[1][b][tid]
                              + s_red[2][b][tid] + s_red[3][b][tid];
            __syncthreads();
        }

        // ---------------- Phase B: delta tile (64 cols) ----------------
        {
            const int lane = tid & 15;          // 4 cols via float4
            const int ds   = tid >> 4;          // 0..31
            const int col  = ct * 64 + lane * 4;
            const float* wo = Wo + (size_t)r * HID_ * C_ + col;

            float4 acc[B_];
            #pragma unroll
            for (int b = 0; b < B_; ++b) acc[b] = make_float4(0.f, 0.f, 0.f, 0.f);

            #pragma unroll 8
            for (int d = ds; d < HID_; d += 32) {
                const float4 w = *reinterpret_cast<const float4*>(wo + (size_t)d * C_);
                #pragma unroll
                for (int b = 0; b < B_; ++b) {
                    const float v = s_tmp[b][d];
                    acc[b].x = fmaf(v, w.x, acc[b].x);
                    acc[b].y = fmaf(v, w.y, acc[b].y);
                    acc[b].z = fmaf(v, w.z, acc[b].z);
                    acc[b].w = fmaf(v, w.w, acc[b].w);
                }
            }

            // reuse s_red as [32][B_][64] (32*4*64 = 8192 floats of the 16384)
            float (*s_rb)[B_][64] = reinterpret_cast<float (*)[B_][64]>(s_red);
            __syncthreads();
            #pragma unroll
            for (int b = 0; b < B_; ++b) {
                s_rb[ds][b][lane * 4 + 0] = acc[b].x;
                s_rb[ds][b][lane * 4 + 1] = acc[b].y;
                s_rb[ds][b][lane * 4 + 2] = acc[b].z;
                s_rb[ds][b][lane * 4 + 3] = acc[b].w;
            }
            __syncthreads();

            if (tid < B_ * 64) {
                const int b = tid >> 6;
                const int c = tid & 63;
                float s = 0.f;
                #pragma unroll
                for (int g = 0; g < 32; ++g) s += s_rb[g][b][c];
                g_delta[((size_t)b * NREG_ + r) * C_ + ct * 64 + c] = s;
            }
        }

    } else {
        // ---------------- perm (stable counting sort via parallel rank) ----
        __shared__ int s_lab[W_];
        const int b = blk - NBLKS_;
        const size_t mask_batch_stride = (size_t)(H_ * DS_) * (W_ * DS_);
        if (tid < W_)
            s_lab[tid] = text_mask[b * mask_batch_stride + (size_t)tid * DS_];
        __syncthreads();
        if (tid < W_) {
            const int lab = s_lab[tid];
            int pos = 0;
            #pragma unroll 8
            for (int w2 = 0; w2 < W_; ++w2) {
                const int l2 = s_lab[w2];
                pos += (l2 < lab) || (l2 == lab && w2 < tid);
            }
            g_lut[b * W_ + pos] = make_int2(tid, (lab - 1) * C_);
        }
    }
}

// ---------------------------------------------------------------------------
// Gather v4 (unchanged, proven 34.7us): each thread produces the same float4
// (w4) for FOUR adjacent h-rows (same b, c => LUT and delta reused 4x).
// ---------------------------------------------------------------------------
#define ROW4_   (W_ / 4)                         // 52
#define H4_     (H_ / 4)                         // 16
#define TOTALQ_ (B_ * C_ * H4_ * ROW4_)          // 1,703,936 quads

__global__ __launch_bounds__(256) void gather_add_kernel(
        const float* __restrict__ image, float* __restrict__ out) {
    const int idx = blockIdx.x * blockDim.x + threadIdx.x;
    if (idx >= TOTALQ_) return;

    const int w4 = idx % ROW4_;
    const int rq = idx / ROW4_;                   // (b, c, h4)
    const int h4 = rq & (H4_ - 1);
    const int c  = (rq >> 4) & (C_ - 1);
    const int b  = rq >> 13;                      // / (C_ * H4_)
    const int w  = w4 * 4;

    const int row = ((b * C_ + c) << 6) + h4 * 4; // (b*C + c)*H + 4*h4

    const int4* lutp = reinterpret_cast<const int4*>(&g_lut[b * W_ + w]);
    const int4 p01 = lutp[0];                     // (src0, roff0, src1, roff1)
    const int4 p23 = lutp[1];                     // (src2, roff2, src3, roff3)

    const float* drow = g_delta + b * (NREG_ * C_) + c;
    const float d0 = __ldg(drow + p01.y);
    const float d1 = __ldg(drow + p01.w);
    const float d2 = __ldg(drow + p23.y);
    const float d3 = __ldg(drow + p23.w);

    const float* imrow = image + (size_t)row * W_;
    float4* out4 = reinterpret_cast<float4*>(out);

    float4 o[4];
    #pragma unroll
    for (int rr = 0; rr < 4; ++rr) {
        const float* im = imrow + rr * W_;
        o[rr].x = __ldg(im + p01.x) + d0;
        o[rr].y = __ldg(im + p01.z) + d1;
        o[rr].z = __ldg(im + p23.x) + d2;
        o[rr].w = __ldg(im + p23.z) + d3;
    }
    #pragma unroll
    for (int rr = 0; rr < 4; ++rr)
        out4[(size_t)(row + rr) * ROW4_ + w4] = o[rr];
}

// ---------------------------------------------------------------------------
// Launch. Input order (metadata): image_feature f32, text_feat f32,
// text_mask i32, Wq f32 (unused), Wk f32 (unused), Wv f32, Wo f32.
// ---------------------------------------------------------------------------
extern "C" void kernel_launch(void* const* d_in, const int* in_sizes, int n_in,
                              void* d_out, int out_size) {
    const float* image     = (const float*)d_in[0];
    const float* text_feat = (const float*)d_in[1];
    const int*   text_mask = (const int*)  d_in[2];
    const float* Wv        = (const float*)d_in[5];
    const float* Wo        = (const float*)d_in[6];
    float* out = (float*)d_out;

    setup_fused<<<NBLKF_, 512>>>(text_feat, Wv, Wo, text_mask);

    const int threads = 256;
    const int blocks = (TOTALQ_ + threads - 1) / threads;
    gather_add_kernel<<<blocks, threads>>>(image, out);
}